// round 13
// baseline (speedup 1.0000x reference)
#include <cuda_runtime.h>
#include <cuda_fp16.h>
#include <math.h>
#include <stdint.h>

#define Bdim 8
#define Sdim 4096
#define Ddim 512
#define Mrows (Bdim * Sdim)
#define NC 128
#define CL (Sdim / NC)
#define NPROJ 2560   /* 5 fused projections */

// ---------------- scratch ----------------
__device__ __half g_proj[(size_t)Mrows * NPROJ];   // omega|mag|gate|qoff|p1
__device__ __half g_phii[(size_t)Mrows * Ddim];
__device__ __half g_xf  [(size_t)Mrows * Ddim];
__device__ __half g_ctxf[(size_t)Mrows * 4 * Ddim];
__device__ __half g_hf  [(size_t)Mrows * 2 * Ddim];
__device__ float4 g_csum[Bdim * NC * Ddim];
__device__ float4 g_coff[Bdim * NC * Ddim];
__device__ __half g_wf[4194304];
__device__ float  g_bcat[NPROJ];

#define OFF_OM   0
#define OFF_MAG  262144
#define OFF_GATE 524288
#define OFF_QOFF 786432
#define OFF_P1   1048576
#define OFF_P2   1310720
#define OFF_O1   1572864
#define OFF_O2   3670016

// ---------------- helpers ----------------
__device__ __forceinline__ uint32_t smem_u32(const void* p) {
    uint32_t a;
    asm("{ .reg .u64 t; cvta.to.shared.u64 t, %1; cvt.u32.u64 %0, t; }" : "=r"(a) : "l"(p));
    return a;
}
#define CP16(so, gp) \
    asm volatile("cp.async.cg.shared.global [%0], [%1], 16;" :: "r"(so), "l"(gp) : "memory")
#define CP_COMMIT() asm volatile("cp.async.commit_group;" ::: "memory")
#define CP_WAIT1()  asm volatile("cp.async.wait_group 1;" ::: "memory")
#define CP_WAIT0()  asm volatile("cp.async.wait_group 0;" ::: "memory")

#define LDSM4(r0, r1, r2, r3, a)                                              \
    asm volatile("ldmatrix.sync.aligned.m8n8.x4.shared.b16 {%0,%1,%2,%3}, [%4];" \
                 : "=r"(r0), "=r"(r1), "=r"(r2), "=r"(r3) : "r"(a))

__device__ __forceinline__ void mma16816(float* c, const uint32_t* a, const uint32_t* b) {
    asm volatile(
        "mma.sync.aligned.m16n8k16.row.col.f32.f16.f16.f32 "
        "{%0,%1,%2,%3}, {%4,%5,%6,%7}, {%8,%9}, {%0,%1,%2,%3};"
        : "+f"(c[0]), "+f"(c[1]), "+f"(c[2]), "+f"(c[3])
        : "r"(a[0]), "r"(a[1]), "r"(a[2]), "r"(a[3]), "r"(b[0]), "r"(b[1]));
}

__device__ __forceinline__ float act_apply(float v, int ACT) {
    if (ACT == 1) return 1.0f / (1.0f + __expf(-v));
    if (ACT == 2) return 5.0f / (1.0f + __expf(-v));
    if (ACT == 3) return 0.5f * v * (1.0f + erff(v * 0.70710678118654752f));
    return v;
}

// load 4 consecutive halfs as float4 (one 8B transaction)
__device__ __forceinline__ float4 ld4h(const __half* p) {
    const __half2* q = (const __half2*)p;
    float2 a = __half22float2(q[0]);
    float2 b = __half22float2(q[1]);
    return make_float4(a.x, a.y, b.x, b.y);
}

// ---------------------------------------------------------------------------
// Prelude (single launch): blocks [0,4096) transpose+convert all 8 weight
// matrices into g_wf[N,K] fp16; blocks [4096,12288) convert x -> fp16
// (8 elems/thread); last 10 blocks concat the 5 projection biases.
// ---------------------------------------------------------------------------
#define WT_BLOCKS 4096
#define FC_BLOCKS 8192
__global__ void __launch_bounds__(256)
prelude_kernel(const float* __restrict__ W0, const float* __restrict__ W1,
               const float* __restrict__ W2, const float* __restrict__ W3,
               const float* __restrict__ W4, const float* __restrict__ W5,
               const float* __restrict__ Wo1, const float* __restrict__ Wo2,
               const float* __restrict__ X,
               const float* __restrict__ b0, const float* __restrict__ b1,
               const float* __restrict__ b2, const float* __restrict__ b3,
               const float* __restrict__ b4,
               __half* __restrict__ T, __half* __restrict__ H,
               float* __restrict__ bout)
{
    __shared__ float tt[32][33];
    const int tx = threadIdx.x, ty = threadIdx.y;
    const int t = blockIdx.x;
    if (t < WT_BLOCKS) {
        const float* W;
        int K, N, n0, k0;
        size_t off;
        if (t < 1536) {
            const int z = t >> 8, rem = t & 255;
            W = (z == 0) ? W0 : (z == 1) ? W1 : (z == 2) ? W2
              : (z == 3) ? W3 : (z == 4) ? W4 : W5;
            K = 512; N = 512; off = (size_t)z * 262144;
            n0 = (rem & 15) * 32; k0 = (rem >> 4) * 32;
        } else if (t < 3584) {
            const int rem = t - 1536;
            W = Wo1; K = 2048; N = 1024; off = OFF_O1;
            n0 = (rem & 31) * 32; k0 = (rem >> 5) * 32;
        } else {
            const int rem = t - 3584;
            W = Wo2; K = 1024; N = 512; off = OFF_O2;
            n0 = (rem & 15) * 32; k0 = (rem >> 4) * 32;
        }
        #pragma unroll
        for (int i = 0; i < 32; i += 8)
            tt[ty + i][tx] = W[(size_t)(k0 + ty + i) * N + n0 + tx];
        __syncthreads();
        #pragma unroll
        for (int i = 0; i < 32; i += 8)
            T[off + (size_t)(n0 + ty + i) * K + k0 + tx] = __float2half(tt[tx][ty + i]);
        return;
    }
    const int tid = ty * 32 + tx;
    if (t < WT_BLOCKS + FC_BLOCKS) {
        const size_t i = ((size_t)(t - WT_BLOCKS) * 256 + tid) * 8;
        float4 v0 = *(const float4*)(X + i);
        float4 v1 = *(const float4*)(X + i + 4);
        *(__half2*)(H + i)     = __floats2half2_rn(v0.x, v0.y);
        *(__half2*)(H + i + 2) = __floats2half2_rn(v0.z, v0.w);
        *(__half2*)(H + i + 4) = __floats2half2_rn(v1.x, v1.y);
        *(__half2*)(H + i + 6) = __floats2half2_rn(v1.z, v1.w);
        return;
    }
    const int i = (t - WT_BLOCKS - FC_BLOCKS) * 256 + tid;
    if (i < NPROJ) {
        const int seg = i >> 9, d = i & 511;
        const float* src = (seg == 0) ? b0 : (seg == 1) ? b1 : (seg == 2) ? b2
                                        : (seg == 3) ? b3 : b4;
        bout[i] = src[d];
    }
}

// ---------------------------------------------------------------------------
// fp16 HMMA GEMM: C = act(A[M,K](lda) @ W + bias) (+resid)
// CTA 128x128, BK=32, 256 thr, warp 64x32, 3-stage cp.async (proven cfg).
// ACT: 0 none, 1 sig, 2 5sig, 3 gelu, 4 resid-add, 5 segmented (bn>>9).
// OUT: 0 fp32, 1 fp16.
// ---------------------------------------------------------------------------
#define STG_ELEMS 10240
#define SMEM_BYTES (3 * STG_ELEMS * 2)

template <int ACT, int OUT>
__global__ void __launch_bounds__(256)
mma_gemm(const __half* __restrict__ A, const __half* __restrict__ W,
         const float* __restrict__ bias, const float* __restrict__ resid,
         float* __restrict__ C, __half* __restrict__ Cf,
         int K, int lda, int ldc)
{
    extern __shared__ __half sm[];
    const int tid = threadIdx.x;
    const int wid = tid >> 5, lane = tid & 31;
    const int wm = wid & 1, wn = wid >> 1;
    const int group = lane >> 2, qp = lane & 3;
    const int bn = blockIdx.x * 128, bm = blockIdx.y * 128;
    const uint32_t smb = smem_u32(sm);
    const int lrow = tid >> 2, lg = tid & 3;

    const uint32_t offA = (uint32_t)((lane & 7) * 40 + ((lane >> 3) & 1) * 320 + (lane >> 4) * 8);
    const uint32_t offB = (uint32_t)((lane & 7) * 40 + ((lane >> 3) & 1) * 8 + (lane >> 4) * 320);

    float acc[4][4][4];
    #pragma unroll
    for (int i = 0; i < 4; i++)
        #pragma unroll
        for (int j = 0; j < 4; j++)
            #pragma unroll
            for (int p = 0; p < 4; p++) acc[i][j][p] = 0.0f;

    const int NT = K >> 5;

#define LOADT(kt, st) do {                                                    \
    _Pragma("unroll")                                                         \
    for (int rep = 0; rep < 2; rep++) {                                       \
        const int row = lrow + rep * 64;                                      \
        const size_t ga = (size_t)(bm + row) * lda + (size_t)(kt) * 32 + lg * 8; \
        const size_t gb = (size_t)(bn + row) * K + (size_t)(kt) * 32 + lg * 8; \
        const uint32_t so = smb + 2u * (uint32_t)((st) * STG_ELEMS + row * 40 + lg * 8); \
        CP16(so, A + ga);                                                     \
        CP16(so + 2 * 5120, W + gb);                                          \
    }                                                                         \
} while (0)

    LOADT(0, 0); CP_COMMIT();
    if (NT > 1) { LOADT(1, 1); CP_COMMIT(); }

    for (int kt = 0; kt < NT; kt++) {
        const int st = kt % 3;
        if (kt + 1 < NT) CP_WAIT1(); else CP_WAIT0();
        __syncthreads();
        if (kt + 2 < NT) { LOADT(kt + 2, (kt + 2) % 3); CP_COMMIT(); }

        const uint32_t As = smb + 2u * (uint32_t)(st * STG_ELEMS);
        const uint32_t Bs = As + 2u * 5120u;
        #pragma unroll
        for (int ks = 0; ks < 2; ks++) {
            uint32_t ah[4][4], bb[2][4];
            #pragma unroll
            for (int i = 0; i < 4; i++) {
                const uint32_t ad = As + 2u * (uint32_t)((wm * 64 + i * 16) * 40 + ks * 16) + 2u * offA;
                LDSM4(ah[i][0], ah[i][1], ah[i][2], ah[i][3], ad);
            }
            #pragma unroll
            for (int jj = 0; jj < 2; jj++) {
                const uint32_t bd = Bs + 2u * (uint32_t)((wn * 32 + jj * 16) * 40 + ks * 16) + 2u * offB;
                LDSM4(bb[jj][0], bb[jj][1], bb[jj][2], bb[jj][3], bd);
            }
            #pragma unroll
            for (int i = 0; i < 4; i++)
                #pragma unroll
                for (int j = 0; j < 4; j++)
                    mma16816(acc[i][j], ah[i], &bb[j >> 1][(j & 1) * 2]);
        }
        __syncthreads();
    }

    // epilogue
    int act = ACT;
    if (ACT == 5) {
        const int seg = bn >> 9;
        act = (seg == 1) ? 2 : (seg == 2) ? 1 : (seg == 4) ? 3 : 0;
    }
    #pragma unroll
    for (int i = 0; i < 4; i++) {
        const int r0 = bm + wm * 64 + i * 16 + group;
        #pragma unroll
        for (int j = 0; j < 4; j++) {
            const int c = bn + wn * 32 + j * 8 + qp * 2;
            const float2 bv = *(const float2*)(bias + c);
            float v0 = acc[i][j][0] + bv.x;
            float v1 = acc[i][j][1] + bv.y;
            float v2 = acc[i][j][2] + bv.x;
            float v3 = acc[i][j][3] + bv.y;
            if (ACT == 4) {
                const float2 ra = *(const float2*)(resid + (size_t)r0 * ldc + c);
                const float2 rb = *(const float2*)(resid + (size_t)(r0 + 8) * ldc + c);
                v0 += ra.x; v1 += ra.y; v2 += rb.x; v3 += rb.y;
            } else {
                v0 = act_apply(v0, act); v1 = act_apply(v1, act);
                v2 = act_apply(v2, act); v3 = act_apply(v3, act);
            }
            if (OUT == 0) {
                *(float2*)(C + (size_t)r0 * ldc + c)       = make_float2(v0, v1);
                *(float2*)(C + (size_t)(r0 + 8) * ldc + c) = make_float2(v2, v3);
            } else {
                *(__half2*)(Cf + (size_t)r0 * ldc + c)       = __floats2half2_rn(v0, v1);
                *(__half2*)(Cf + (size_t)(r0 + 8) * ldc + c) = __floats2half2_rn(v2, v3);
            }
        }
    }
#undef LOADT
}

// ---------------- scan passes ----------------
// proj row layout: [omega(0) | mag(512) | gate(1024) | qoff(1536) | p1(2048)]
// passA: 256 thr/block, block covers 2 chunks; 4 d-channels/thread (8B loads)
__global__ void __launch_bounds__(256)
passA_kernel(const __half* __restrict__ xf, const __half* __restrict__ proj,
             const __half* __restrict__ phii, const float* __restrict__ iscale,
             float4* __restrict__ csum)
{
    const int b = blockIdx.x / (NC / 2);
    const int cpair = blockIdx.x % (NC / 2);
    const int half = threadIdx.x >> 7;      // 0 or 1 -> which chunk
    const int t = threadIdx.x & 127;
    const int c = cpair * 2 + half;
    const int d0 = t * 4;
    const float4 sc4 = *(const float4*)(iscale + d0);
    const float sc[4] = {fabsf(sc4.x), fabsf(sc4.y), fabsf(sc4.z), fabsf(sc4.w)};
    size_t row = (size_t)b * Sdim + (size_t)c * CL;
    size_t idx = row * Ddim + d0;
    size_t pidx = row * NPROJ + d0;
    float ri[4] = {0, 0, 0, 0}, rm[4] = {0, 0, 0, 0};
    float rA[4] = {0, 0, 0, 0}, rB[4] = {0, 0, 0, 0};
    #pragma unroll 4
    for (int s = 0; s < CL; s++, idx += Ddim, pidx += NPROJ) {
        const float4 om = ld4h(proj + pidx);
        const float4 m  = ld4h(proj + pidx + 512);
        const float4 g  = ld4h(proj + pidx + 1024);
        const float4 xv = ld4h(xf + idx);
        const float4 pi = ld4h(phii + idx);
        const float omv[4] = {om.x, om.y, om.z, om.w};
        const float mv[4]  = {m.x, m.y, m.z, m.w};
        const float gv[4]  = {g.x, g.y, g.z, g.w};
        const float xvv[4] = {xv.x, xv.y, xv.z, xv.w};
        const float piv[4] = {pi.x, pi.y, pi.z, pi.w};
        #pragma unroll
        for (int ch = 0; ch < 4; ch++) {
            ri[ch] += gv[ch] * omv[ch] * sc[ch];
            float sp, cp;
            __sincosf(piv[ch] + ri[ch], &sp, &cp);
            const float wc = mv[ch] * xvv[ch];
            rA[ch] += wc * cp; rB[ch] += wc * sp; rm[ch] += mv[ch];
        }
    }
    const size_t cb = ((size_t)b * NC + c) * Ddim + d0;
    #pragma unroll
    for (int ch = 0; ch < 4; ch++)
        csum[cb + ch] = make_float4(ri[ch], rm[ch], rA[ch], rB[ch]);
}

__global__ void __launch_bounds__(Ddim)
passB_kernel(const float4* __restrict__ csum, float4* __restrict__ coff)
{
    const int b = blockIdx.x, d = threadIdx.x;
    float oi = 0.f, om = 0.f, omr = 0.f, omi = 0.f;
    #pragma unroll 4
    for (int c = 0; c < NC; c++) {
        const size_t i = ((size_t)b * NC + c) * Ddim + d;
        coff[i] = make_float4(oi, om, omr, omi);
        float4 s = csum[i];
        float st, ct;
        __sincosf(oi, &st, &ct);
        omr += ct * s.z - st * s.w;
        omi += st * s.z + ct * s.w;
        oi += s.x; om += s.y;
    }
}

__global__ void __launch_bounds__(256)
passC_kernel(const __half* __restrict__ xf, const __half* __restrict__ proj,
             const __half* __restrict__ phii,
             const float* __restrict__ iscale, const float* __restrict__ lng,
             const float* __restrict__ lnb, const float4* __restrict__ coff,
             __half* __restrict__ ctx)
{
    __shared__ float2 warpred[2][8];
    const int b = blockIdx.x / NC, c = blockIdx.x % NC;
    const int d0 = threadIdx.x * 2;
    const int lane = threadIdx.x & 31, wid = threadIdx.x >> 5;
    const float2 sc2 = *(const float2*)(iscale + d0);
    const float sca = fabsf(sc2.x), scb = fabsf(sc2.y);
    float2 lg0 = *(const float2*)(lng + d0);
    float2 lg1 = *(const float2*)(lng + Ddim + d0);
    float2 lg2 = *(const float2*)(lng + 2 * Ddim + d0);
    float2 lg3 = *(const float2*)(lng + 3 * Ddim + d0);
    float2 lb0 = *(const float2*)(lnb + d0);
    float2 lb1 = *(const float2*)(lnb + Ddim + d0);
    float2 lb2 = *(const float2*)(lnb + 2 * Ddim + d0);
    float2 lb3 = *(const float2*)(lnb + 3 * Ddim + d0);

    float4 ofa = coff[(size_t)blockIdx.x * Ddim + d0];
    float4 ofb = coff[(size_t)blockIdx.x * Ddim + d0 + 1];
    float ria = ofa.x, rma = ofa.y, rra = ofa.z, rib_ = ofa.w;
    float rib = ofb.x, rmb = ofb.y, rrb = ofb.z, rib2 = ofb.w;
    size_t row   = (size_t)b * Sdim + (size_t)c * CL;
    size_t idx   = row * Ddim + d0;
    size_t pidx  = row * NPROJ + d0;
    size_t cbase = row * (4 * Ddim) + d0;

    for (int s = 0; s < CL; s++, idx += Ddim, pidx += NPROJ, cbase += 4 * Ddim) {
        const float2 om = __half22float2(*(const __half2*)(proj + pidx));
        const float2 m  = __half22float2(*(const __half2*)(proj + pidx + 512));
        const float2 g  = __half22float2(*(const __half2*)(proj + pidx + 1024));
        const float2 qo = __half22float2(*(const __half2*)(proj + pidx + 1536));
        const float2 xv = __half22float2(*(const __half2*)(xf + idx));
        const float2 pi = __half22float2(*(const __half2*)(phii + idx));

        ria += g.x * om.x * sca;
        rib += g.y * om.y * scb;
        const float phia = pi.x + ria, phib = pi.y + rib;
        float spa, cpa, spb, cpb;
        __sincosf(phia, &spa, &cpa);
        __sincosf(phib, &spb, &cpb);
        const float wca = m.x * xv.x, wcb = m.y * xv.y;
        rra  += wca * cpa; rib_ += wca * spa; rma += m.x;
        rrb  += wcb * cpb; rib2 += wcb * spb; rmb += m.y;
        const float rqa = rsqrtf(rma + 1e-8f), rqb = rsqrtf(rmb + 1e-8f);
        const float mra = rra * rqa, mia = rib_ * rqa;
        const float mrb = rrb * rqb, mib = rib2 * rqb;
        float sqa, cqa, sqb, cqb;
        __sincosf(phia + qo.x, &sqa, &cqa);
        __sincosf(phib + qo.y, &sqb, &cqb);
        const float v0a = xv.x * cpa, v1a = xv.x * spa;
        const float v2a = mra * cqa + mia * sqa;
        const float v3a = mia * cqa - mra * sqa;
        const float v0b = xv.y * cpb, v1b = xv.y * spb;
        const float v2b = mrb * cqb + mib * sqb;
        const float v3b = mib * cqb - mrb * sqb;

        float lsum = v0a + v1a + v2a + v3a + v0b + v1b + v2b + v3b;
        float lss  = v0a * v0a + v1a * v1a + v2a * v2a + v3a * v3a
                   + v0b * v0b + v1b * v1b + v2b * v2b + v3b * v3b;
        #pragma unroll
        for (int o = 16; o > 0; o >>= 1) {
            lsum += __shfl_down_sync(0xffffffffu, lsum, o);
            lss  += __shfl_down_sync(0xffffffffu, lss, o);
        }
        const int pb = s & 1;
        if (lane == 0) warpred[pb][wid] = make_float2(lsum, lss);
        __syncthreads();
        float2 t = warpred[pb][lane & 7];
        #pragma unroll
        for (int o = 4; o > 0; o >>= 1) {
            t.x += __shfl_xor_sync(0xffffffffu, t.x, o);
            t.y += __shfl_xor_sync(0xffffffffu, t.y, o);
        }
        const float mean = t.x * (1.0f / 2048.0f);
        const float var  = t.y * (1.0f / 2048.0f) - mean * mean;
        const float rstd = rsqrtf(var + 1e-5f);

        *(__half2*)(ctx + cbase) = __floats2half2_rn(
            (v0a - mean) * rstd * lg0.x + lb0.x, (v0b - mean) * rstd * lg0.y + lb0.y);
        *(__half2*)(ctx + cbase + Ddim) = __floats2half2_rn(
            (v1a - mean) * rstd * lg1.x + lb1.x, (v1b - mean) * rstd * lg1.y + lb1.y);
        *(__half2*)(ctx + cbase + 2 * Ddim) = __floats2half2_rn(
            (v2a - mean) * rstd * lg2.x + lb2.x, (v2b - mean) * rstd * lg2.y + lb2.y);
        *(__half2*)(ctx + cbase + 3 * Ddim) = __floats2half2_rn(
            (v3a - mean) * rstd * lg3.x + lb3.x, (v3b - mean) * rstd * lg3.y + lb3.y);
    }
}

// ---------------- launch ----------------
extern "C" void kernel_launch(void* const* d_in, const int* in_sizes, int n_in,
                              void* d_out, int out_size)
{
    const float* x       = (const float*)d_in[0];
    const float* W_omega = (const float*)d_in[1];
    const float* b_omega = (const float*)d_in[2];
    const float* W_p1    = (const float*)d_in[3];
    const float* b_p1    = (const float*)d_in[4];
    const float* W_p2    = (const float*)d_in[5];
    const float* b_p2    = (const float*)d_in[6];
    const float* W_gate  = (const float*)d_in[7];
    const float* b_gate  = (const float*)d_in[8];
    const float* iscale  = (const float*)d_in[9];
    const float* W_mag   = (const float*)d_in[10];
    const float* b_mag   = (const float*)d_in[11];
    const float* W_qoff  = (const float*)d_in[12];
    const float* b_qoff  = (const float*)d_in[13];
    const float* ln_g    = (const float*)d_in[14];
    const float* ln_b    = (const float*)d_in[15];
    const float* W_o1    = (const float*)d_in[16];
    const float* b_o1    = (const float*)d_in[17];
    const float* W_o2    = (const float*)d_in[18];
    const float* b_o2    = (const float*)d_in[19];
    float* out = (float*)d_out;

    __half *p_proj, *p_phii, *p_xf, *p_ctxf, *p_hf, *p_wf;
    float *p_bcat;
    float4 *p_csum, *p_coff;
    cudaGetSymbolAddress((void**)&p_proj,  g_proj);
    cudaGetSymbolAddress((void**)&p_phii,  g_phii);
    cudaGetSymbolAddress((void**)&p_xf,    g_xf);
    cudaGetSymbolAddress((void**)&p_ctxf,  g_ctxf);
    cudaGetSymbolAddress((void**)&p_hf,    g_hf);
    cudaGetSymbolAddress((void**)&p_wf,    g_wf);
    cudaGetSymbolAddress((void**)&p_bcat,  g_bcat);
    cudaGetSymbolAddress((void**)&p_csum,  g_csum);
    cudaGetSymbolAddress((void**)&p_coff,  g_coff);

    cudaFuncSetAttribute(mma_gemm<5,1>, cudaFuncAttributeMaxDynamicSharedMemorySize, SMEM_BYTES);
    cudaFuncSetAttribute(mma_gemm<0,1>, cudaFuncAttributeMaxDynamicSharedMemorySize, SMEM_BYTES);
    cudaFuncSetAttribute(mma_gemm<3,1>, cudaFuncAttributeMaxDynamicSharedMemorySize, SMEM_BYTES);
    cudaFuncSetAttribute(mma_gemm<4,0>, cudaFuncAttributeMaxDynamicSharedMemorySize, SMEM_BYTES);

    // Single prelude launch: all weight transposes + x conversion + bias concat
    prelude_kernel<<<WT_BLOCKS + FC_BLOCKS + (NPROJ + 255) / 256, dim3(32, 8)>>>(
        W_omega, W_mag, W_gate, W_qoff, W_p1, W_p2, W_o1, W_o2,
        x, b_omega, b_mag, b_gate, b_qoff, b_p1,
        p_wf, p_xf, p_bcat);

    const dim3 blk(256);

    // Fused 5-projection GEMM: [M,512] @ [512,2560] -> proj (segmented act)
    mma_gemm<5,1><<<dim3(NPROJ / 128, Mrows / 128), blk, SMEM_BYTES>>>(
        p_xf, p_wf + OFF_OM, p_bcat, 0, 0, p_proj, 512, 512, NPROJ);

    // p2: phi_init = p1seg @ W_p2 + b_p2  (A strided out of proj buffer)
    mma_gemm<0,1><<<dim3(4, Mrows / 128), blk, SMEM_BYTES>>>(
        p_proj + 2048, p_wf + OFF_P2, b_p2, 0, 0, p_phii, 512, NPROJ, 512);

    passA_kernel<<<Bdim * NC / 2, 256>>>(p_xf, p_proj, p_phii, iscale, p_csum);
    passB_kernel<<<Bdim, Ddim>>>(p_csum, p_coff);
    passC_kernel<<<Bdim * NC, 256>>>(p_xf, p_proj, p_phii, iscale, ln_g, ln_b,
                                     p_coff, p_ctxf);

    mma_gemm<3,1><<<dim3(8, Mrows / 128), blk, SMEM_BYTES>>>(
        p_ctxf, p_wf + OFF_O1, b_o1, 0, 0, p_hf, 2048, 2048, 1024);
    mma_gemm<4,0><<<dim3(4, Mrows / 128), blk, SMEM_BYTES>>>(
        p_hf, p_wf + OFF_O2, b_o2, x, out, 0, 1024, 1024, 512);
}

// round 14
// speedup vs baseline: 1.0180x; 1.0180x over previous
#include <cuda_runtime.h>
#include <cuda_fp16.h>
#include <math.h>
#include <stdint.h>

#define Bdim 8
#define Sdim 4096
#define Ddim 512
#define Mrows (Bdim * Sdim)
#define NC 128
#define CL (Sdim / NC)
#define NPROJ 2560   /* 5 fused projections */

// ---------------- scratch ----------------
__device__ __half g_proj[(size_t)Mrows * NPROJ];   // omega|mag|gate|qoff|p1
__device__ __half g_phii[(size_t)Mrows * Ddim];
__device__ __half g_xf  [(size_t)Mrows * Ddim];
__device__ __half g_ctxf[(size_t)Mrows * 4 * Ddim];
__device__ __half g_hf  [(size_t)Mrows * 2 * Ddim];
__device__ float4 g_csum[Bdim * NC * Ddim];
__device__ float4 g_coff[Bdim * NC * Ddim];
__device__ __half g_wf[4194304];
__device__ float  g_bcat[NPROJ];

#define OFF_OM   0
#define OFF_MAG  262144
#define OFF_GATE 524288
#define OFF_QOFF 786432
#define OFF_P1   1048576
#define OFF_P2   1310720
#define OFF_O1   1572864
#define OFF_O2   3670016

// ---------------- helpers ----------------
__device__ __forceinline__ uint32_t smem_u32(const void* p) {
    uint32_t a;
    asm("{ .reg .u64 t; cvta.to.shared.u64 t, %1; cvt.u32.u64 %0, t; }" : "=r"(a) : "l"(p));
    return a;
}
#define CP16(so, gp) \
    asm volatile("cp.async.cg.shared.global [%0], [%1], 16;" :: "r"(so), "l"(gp) : "memory")
#define CP_COMMIT() asm volatile("cp.async.commit_group;" ::: "memory")
#define CP_WAIT1()  asm volatile("cp.async.wait_group 1;" ::: "memory")
#define CP_WAIT0()  asm volatile("cp.async.wait_group 0;" ::: "memory")

#define LDSM4(r0, r1, r2, r3, a)                                              \
    asm volatile("ldmatrix.sync.aligned.m8n8.x4.shared.b16 {%0,%1,%2,%3}, [%4];" \
                 : "=r"(r0), "=r"(r1), "=r"(r2), "=r"(r3) : "r"(a))

__device__ __forceinline__ void mma16816(float* c, const uint32_t* a, const uint32_t* b) {
    asm volatile(
        "mma.sync.aligned.m16n8k16.row.col.f32.f16.f16.f32 "
        "{%0,%1,%2,%3}, {%4,%5,%6,%7}, {%8,%9}, {%0,%1,%2,%3};"
        : "+f"(c[0]), "+f"(c[1]), "+f"(c[2]), "+f"(c[3])
        : "r"(a[0]), "r"(a[1]), "r"(a[2]), "r"(a[3]), "r"(b[0]), "r"(b[1]));
}

__device__ __forceinline__ float act_apply(float v, int ACT) {
    if (ACT == 1) return 1.0f / (1.0f + __expf(-v));
    if (ACT == 2) return 5.0f / (1.0f + __expf(-v));
    if (ACT == 3) return 0.5f * v * (1.0f + erff(v * 0.70710678118654752f));
    return v;
}

// ---------------------------------------------------------------------------
// Prelude (single launch): blocks [0,4096) transpose+convert all 8 weight
// matrices into g_wf[N,K] fp16; blocks [4096,12288) convert x -> fp16
// (8 elems/thread); last 10 blocks concat the 5 projection biases.
// ---------------------------------------------------------------------------
#define WT_BLOCKS 4096
#define FC_BLOCKS 8192
__global__ void __launch_bounds__(256)
prelude_kernel(const float* __restrict__ W0, const float* __restrict__ W1,
               const float* __restrict__ W2, const float* __restrict__ W3,
               const float* __restrict__ W4, const float* __restrict__ W5,
               const float* __restrict__ Wo1, const float* __restrict__ Wo2,
               const float* __restrict__ X,
               const float* __restrict__ b0, const float* __restrict__ b1,
               const float* __restrict__ b2, const float* __restrict__ b3,
               const float* __restrict__ b4,
               __half* __restrict__ T, __half* __restrict__ H,
               float* __restrict__ bout)
{
    __shared__ float tt[32][33];
    const int tx = threadIdx.x, ty = threadIdx.y;
    const int t = blockIdx.x;
    if (t < WT_BLOCKS) {
        const float* W;
        int K, N, n0, k0;
        size_t off;
        if (t < 1536) {
            const int z = t >> 8, rem = t & 255;
            W = (z == 0) ? W0 : (z == 1) ? W1 : (z == 2) ? W2
              : (z == 3) ? W3 : (z == 4) ? W4 : W5;
            K = 512; N = 512; off = (size_t)z * 262144;
            n0 = (rem & 15) * 32; k0 = (rem >> 4) * 32;
        } else if (t < 3584) {
            const int rem = t - 1536;
            W = Wo1; K = 2048; N = 1024; off = OFF_O1;
            n0 = (rem & 31) * 32; k0 = (rem >> 5) * 32;
        } else {
            const int rem = t - 3584;
            W = Wo2; K = 1024; N = 512; off = OFF_O2;
            n0 = (rem & 15) * 32; k0 = (rem >> 4) * 32;
        }
        #pragma unroll
        for (int i = 0; i < 32; i += 8)
            tt[ty + i][tx] = W[(size_t)(k0 + ty + i) * N + n0 + tx];
        __syncthreads();
        #pragma unroll
        for (int i = 0; i < 32; i += 8)
            T[off + (size_t)(n0 + ty + i) * K + k0 + tx] = __float2half(tt[tx][ty + i]);
        return;
    }
    const int tid = ty * 32 + tx;
    if (t < WT_BLOCKS + FC_BLOCKS) {
        const size_t i = ((size_t)(t - WT_BLOCKS) * 256 + tid) * 8;
        float4 v0 = *(const float4*)(X + i);
        float4 v1 = *(const float4*)(X + i + 4);
        *(__half2*)(H + i)     = __floats2half2_rn(v0.x, v0.y);
        *(__half2*)(H + i + 2) = __floats2half2_rn(v0.z, v0.w);
        *(__half2*)(H + i + 4) = __floats2half2_rn(v1.x, v1.y);
        *(__half2*)(H + i + 6) = __floats2half2_rn(v1.z, v1.w);
        return;
    }
    const int i = (t - WT_BLOCKS - FC_BLOCKS) * 256 + tid;
    if (i < NPROJ) {
        const int seg = i >> 9, d = i & 511;
        const float* src = (seg == 0) ? b0 : (seg == 1) ? b1 : (seg == 2) ? b2
                                        : (seg == 3) ? b3 : b4;
        bout[i] = src[d];
    }
}

// ---------------------------------------------------------------------------
// fp16 HMMA GEMM: C = act(A[M,K](lda) @ W + bias) (+resid)
// CTA 128x128, BK=32, 256 thr, warp 64x32, 3-stage cp.async (proven cfg).
// ACT: 0 none, 1 sig, 2 5sig, 3 gelu, 4 resid-add, 5 segmented (bn>>9).
// OUT: 0 fp32, 1 fp16.
// ---------------------------------------------------------------------------
#define STG_ELEMS 10240
#define SMEM_BYTES (3 * STG_ELEMS * 2)

template <int ACT, int OUT>
__global__ void __launch_bounds__(256)
mma_gemm(const __half* __restrict__ A, const __half* __restrict__ W,
         const float* __restrict__ bias, const float* __restrict__ resid,
         float* __restrict__ C, __half* __restrict__ Cf,
         int K, int lda, int ldc)
{
    extern __shared__ __half sm[];
    const int tid = threadIdx.x;
    const int wid = tid >> 5, lane = tid & 31;
    const int wm = wid & 1, wn = wid >> 1;
    const int group = lane >> 2, qp = lane & 3;
    const int bn = blockIdx.x * 128, bm = blockIdx.y * 128;
    const uint32_t smb = smem_u32(sm);
    const int lrow = tid >> 2, lg = tid & 3;

    const uint32_t offA = (uint32_t)((lane & 7) * 40 + ((lane >> 3) & 1) * 320 + (lane >> 4) * 8);
    const uint32_t offB = (uint32_t)((lane & 7) * 40 + ((lane >> 3) & 1) * 8 + (lane >> 4) * 320);

    float acc[4][4][4];
    #pragma unroll
    for (int i = 0; i < 4; i++)
        #pragma unroll
        for (int j = 0; j < 4; j++)
            #pragma unroll
            for (int p = 0; p < 4; p++) acc[i][j][p] = 0.0f;

    const int NT = K >> 5;

#define LOADT(kt, st) do {                                                    \
    _Pragma("unroll")                                                         \
    for (int rep = 0; rep < 2; rep++) {                                       \
        const int row = lrow + rep * 64;                                      \
        const size_t ga = (size_t)(bm + row) * lda + (size_t)(kt) * 32 + lg * 8; \
        const size_t gb = (size_t)(bn + row) * K + (size_t)(kt) * 32 + lg * 8; \
        const uint32_t so = smb + 2u * (uint32_t)((st) * STG_ELEMS + row * 40 + lg * 8); \
        CP16(so, A + ga);                                                     \
        CP16(so + 2 * 5120, W + gb);                                          \
    }                                                                         \
} while (0)

    LOADT(0, 0); CP_COMMIT();
    if (NT > 1) { LOADT(1, 1); CP_COMMIT(); }

    for (int kt = 0; kt < NT; kt++) {
        const int st = kt % 3;
        if (kt + 1 < NT) CP_WAIT1(); else CP_WAIT0();
        __syncthreads();
        if (kt + 2 < NT) { LOADT(kt + 2, (kt + 2) % 3); CP_COMMIT(); }

        const uint32_t As = smb + 2u * (uint32_t)(st * STG_ELEMS);
        const uint32_t Bs = As + 2u * 5120u;
        #pragma unroll
        for (int ks = 0; ks < 2; ks++) {
            uint32_t ah[4][4], bb[2][4];
            #pragma unroll
            for (int i = 0; i < 4; i++) {
                const uint32_t ad = As + 2u * (uint32_t)((wm * 64 + i * 16) * 40 + ks * 16) + 2u * offA;
                LDSM4(ah[i][0], ah[i][1], ah[i][2], ah[i][3], ad);
            }
            #pragma unroll
            for (int jj = 0; jj < 2; jj++) {
                const uint32_t bd = Bs + 2u * (uint32_t)((wn * 32 + jj * 16) * 40 + ks * 16) + 2u * offB;
                LDSM4(bb[jj][0], bb[jj][1], bb[jj][2], bb[jj][3], bd);
            }
            #pragma unroll
            for (int i = 0; i < 4; i++)
                #pragma unroll
                for (int j = 0; j < 4; j++)
                    mma16816(acc[i][j], ah[i], &bb[j >> 1][(j & 1) * 2]);
        }
        __syncthreads();
    }

    // epilogue
    int act = ACT;
    if (ACT == 5) {
        const int seg = bn >> 9;
        act = (seg == 1) ? 2 : (seg == 2) ? 1 : (seg == 4) ? 3 : 0;
    }
    #pragma unroll
    for (int i = 0; i < 4; i++) {
        const int r0 = bm + wm * 64 + i * 16 + group;
        #pragma unroll
        for (int j = 0; j < 4; j++) {
            const int c = bn + wn * 32 + j * 8 + qp * 2;
            const float2 bv = *(const float2*)(bias + c);
            float v0 = acc[i][j][0] + bv.x;
            float v1 = acc[i][j][1] + bv.y;
            float v2 = acc[i][j][2] + bv.x;
            float v3 = acc[i][j][3] + bv.y;
            if (ACT == 4) {
                const float2 ra = *(const float2*)(resid + (size_t)r0 * ldc + c);
                const float2 rb = *(const float2*)(resid + (size_t)(r0 + 8) * ldc + c);
                v0 += ra.x; v1 += ra.y; v2 += rb.x; v3 += rb.y;
            } else {
                v0 = act_apply(v0, act); v1 = act_apply(v1, act);
                v2 = act_apply(v2, act); v3 = act_apply(v3, act);
            }
            if (OUT == 0) {
                *(float2*)(C + (size_t)r0 * ldc + c)       = make_float2(v0, v1);
                *(float2*)(C + (size_t)(r0 + 8) * ldc + c) = make_float2(v2, v3);
            } else {
                *(__half2*)(Cf + (size_t)r0 * ldc + c)       = __floats2half2_rn(v0, v1);
                *(__half2*)(Cf + (size_t)(r0 + 8) * ldc + c) = __floats2half2_rn(v2, v3);
            }
        }
    }
#undef LOADT
}

// ---------------- scan passes (R12 champion config) ----------------
// proj row layout: [omega(0) | mag(512) | gate(1024) | qoff(1536) | p1(2048)]
__global__ void __launch_bounds__(256)
passA_kernel(const __half* __restrict__ xf, const __half* __restrict__ proj,
             const __half* __restrict__ phii, const float* __restrict__ iscale,
             float4* __restrict__ csum)
{
    const int b = blockIdx.x / NC, c = blockIdx.x % NC;
    const int d0 = threadIdx.x * 2;
    const float2 sc2 = *(const float2*)(iscale + d0);
    const float sca = fabsf(sc2.x), scb = fabsf(sc2.y);
    size_t row = (size_t)b * Sdim + (size_t)c * CL;
    size_t idx = row * Ddim + d0;
    size_t pidx = row * NPROJ + d0;
    float ria = 0.f, rma = 0.f, rAa = 0.f, rBa = 0.f;
    float rib = 0.f, rmb = 0.f, rAb = 0.f, rBb = 0.f;
    #pragma unroll 2
    for (int s = 0; s < CL; s++, idx += Ddim, pidx += NPROJ) {
        const float2 om = __half22float2(*(const __half2*)(proj + pidx));
        const float2 m  = __half22float2(*(const __half2*)(proj + pidx + 512));
        const float2 g  = __half22float2(*(const __half2*)(proj + pidx + 1024));
        const float2 xv = __half22float2(*(const __half2*)(xf + idx));
        const float2 pi = __half22float2(*(const __half2*)(phii + idx));
        ria += g.x * om.x * sca;
        rib += g.y * om.y * scb;
        float spa, cpa, spb, cpb;
        __sincosf(pi.x + ria, &spa, &cpa);
        __sincosf(pi.y + rib, &spb, &cpb);
        const float wca = m.x * xv.x, wcb = m.y * xv.y;
        rAa += wca * cpa; rBa += wca * spa; rma += m.x;
        rAb += wcb * cpb; rBb += wcb * spb; rmb += m.y;
    }
    csum[(size_t)blockIdx.x * Ddim + d0]     = make_float4(ria, rma, rAa, rBa);
    csum[(size_t)blockIdx.x * Ddim + d0 + 1] = make_float4(rib, rmb, rAb, rBb);
}

__global__ void __launch_bounds__(Ddim)
passB_kernel(const float4* __restrict__ csum, float4* __restrict__ coff)
{
    const int b = blockIdx.x, d = threadIdx.x;
    float oi = 0.f, om = 0.f, omr = 0.f, omi = 0.f;
    #pragma unroll 4
    for (int c = 0; c < NC; c++) {
        const size_t i = ((size_t)b * NC + c) * Ddim + d;
        coff[i] = make_float4(oi, om, omr, omi);
        float4 s = csum[i];
        float st, ct;
        __sincosf(oi, &st, &ct);
        omr += ct * s.z - st * s.w;
        omi += st * s.z + ct * s.w;
        oi += s.x; om += s.y;
    }
}

// passC: software-pipelined — next iteration's gmem loads issued before the
// LN barrier so their latency overlaps the reduction.
__global__ void __launch_bounds__(256)
passC_kernel(const __half* __restrict__ xf, const __half* __restrict__ proj,
             const __half* __restrict__ phii,
             const float* __restrict__ iscale, const float* __restrict__ lng,
             const float* __restrict__ lnb, const float4* __restrict__ coff,
             __half* __restrict__ ctx)
{
    __shared__ float2 warpred[2][8];
    const int b = blockIdx.x / NC, c = blockIdx.x % NC;
    const int d0 = threadIdx.x * 2;
    const int lane = threadIdx.x & 31, wid = threadIdx.x >> 5;
    const float2 sc2 = *(const float2*)(iscale + d0);
    const float sca = fabsf(sc2.x), scb = fabsf(sc2.y);
    float2 lg0 = *(const float2*)(lng + d0);
    float2 lg1 = *(const float2*)(lng + Ddim + d0);
    float2 lg2 = *(const float2*)(lng + 2 * Ddim + d0);
    float2 lg3 = *(const float2*)(lng + 3 * Ddim + d0);
    float2 lb0 = *(const float2*)(lnb + d0);
    float2 lb1 = *(const float2*)(lnb + Ddim + d0);
    float2 lb2 = *(const float2*)(lnb + 2 * Ddim + d0);
    float2 lb3 = *(const float2*)(lnb + 3 * Ddim + d0);

    float4 ofa = coff[(size_t)blockIdx.x * Ddim + d0];
    float4 ofb = coff[(size_t)blockIdx.x * Ddim + d0 + 1];
    float ria = ofa.x, rma = ofa.y, rra = ofa.z, rib_ = ofa.w;
    float rib = ofb.x, rmb = ofb.y, rrb = ofb.z, rib2 = ofb.w;
    size_t row   = (size_t)b * Sdim + (size_t)c * CL;
    size_t idx   = row * Ddim + d0;
    size_t pidx  = row * NPROJ + d0;
    size_t cbase = row * (4 * Ddim) + d0;

    // prologue loads for s = 0
    __half2 h_om = *(const __half2*)(proj + pidx);
    __half2 h_m  = *(const __half2*)(proj + pidx + 512);
    __half2 h_g  = *(const __half2*)(proj + pidx + 1024);
    __half2 h_qo = *(const __half2*)(proj + pidx + 1536);
    __half2 h_xv = *(const __half2*)(xf + idx);
    __half2 h_pi = *(const __half2*)(phii + idx);

    for (int s = 0; s < CL; s++, cbase += 4 * Ddim) {
        const float2 om = __half22float2(h_om);
        const float2 m  = __half22float2(h_m);
        const float2 g  = __half22float2(h_g);
        const float2 qo = __half22float2(h_qo);
        const float2 xv = __half22float2(h_xv);
        const float2 pi = __half22float2(h_pi);

        // issue next iteration's loads NOW (latency hides behind trig+barrier)
        if (s + 1 < CL) {
            idx += Ddim; pidx += NPROJ;
            h_om = *(const __half2*)(proj + pidx);
            h_m  = *(const __half2*)(proj + pidx + 512);
            h_g  = *(const __half2*)(proj + pidx + 1024);
            h_qo = *(const __half2*)(proj + pidx + 1536);
            h_xv = *(const __half2*)(xf + idx);
            h_pi = *(const __half2*)(phii + idx);
        }

        ria += g.x * om.x * sca;
        rib += g.y * om.y * scb;
        const float phia = pi.x + ria, phib = pi.y + rib;
        float spa, cpa, spb, cpb;
        __sincosf(phia, &spa, &cpa);
        __sincosf(phib, &spb, &cpb);
        const float wca = m.x * xv.x, wcb = m.y * xv.y;
        rra  += wca * cpa; rib_ += wca * spa; rma += m.x;
        rrb  += wcb * cpb; rib2 += wcb * spb; rmb += m.y;
        const float rqa = rsqrtf(rma + 1e-8f), rqb = rsqrtf(rmb + 1e-8f);
        const float mra = rra * rqa, mia = rib_ * rqa;
        const float mrb = rrb * rqb, mib = rib2 * rqb;
        float sqa, cqa, sqb, cqb;
        __sincosf(phia + qo.x, &sqa, &cqa);
        __sincosf(phib + qo.y, &sqb, &cqb);
        const float v0a = xv.x * cpa, v1a = xv.x * spa;
        const float v2a = mra * cqa + mia * sqa;
        const float v3a = mia * cqa - mra * sqa;
        const float v0b = xv.y * cpb, v1b = xv.y * spb;
        const float v2b = mrb * cqb + mib * sqb;
        const float v3b = mib * cqb - mrb * sqb;

        float lsum = v0a + v1a + v2a + v3a + v0b + v1b + v2b + v3b;
        float lss  = v0a * v0a + v1a * v1a + v2a * v2a + v3a * v3a
                   + v0b * v0b + v1b * v1b + v2b * v2b + v3b * v3b;
        #pragma unroll
        for (int o = 16; o > 0; o >>= 1) {
            lsum += __shfl_down_sync(0xffffffffu, lsum, o);
            lss  += __shfl_down_sync(0xffffffffu, lss, o);
        }
        const int pb = s & 1;
        if (lane == 0) warpred[pb][wid] = make_float2(lsum, lss);
        __syncthreads();
        float2 t = warpred[pb][lane & 7];
        #pragma unroll
        for (int o = 4; o > 0; o >>= 1) {
            t.x += __shfl_xor_sync(0xffffffffu, t.x, o);
            t.y += __shfl_xor_sync(0xffffffffu, t.y, o);
        }
        const float mean = t.x * (1.0f / 2048.0f);
        const float var  = t.y * (1.0f / 2048.0f) - mean * mean;
        const float rstd = rsqrtf(var + 1e-5f);

        *(__half2*)(ctx + cbase) = __floats2half2_rn(
            (v0a - mean) * rstd * lg0.x + lb0.x, (v0b - mean) * rstd * lg0.y + lb0.y);
        *(__half2*)(ctx + cbase + Ddim) = __floats2half2_rn(
            (v1a - mean) * rstd * lg1.x + lb1.x, (v1b - mean) * rstd * lg1.y + lb1.y);
        *(__half2*)(ctx + cbase + 2 * Ddim) = __floats2half2_rn(
            (v2a - mean) * rstd * lg2.x + lb2.x, (v2b - mean) * rstd * lg2.y + lb2.y);
        *(__half2*)(ctx + cbase + 3 * Ddim) = __floats2half2_rn(
            (v3a - mean) * rstd * lg3.x + lb3.x, (v3b - mean) * rstd * lg3.y + lb3.y);
    }
}

// ---------------- launch ----------------
extern "C" void kernel_launch(void* const* d_in, const int* in_sizes, int n_in,
                              void* d_out, int out_size)
{
    const float* x       = (const float*)d_in[0];
    const float* W_omega = (const float*)d_in[1];
    const float* b_omega = (const float*)d_in[2];
    const float* W_p1    = (const float*)d_in[3];
    const float* b_p1    = (const float*)d_in[4];
    const float* W_p2    = (const float*)d_in[5];
    const float* b_p2    = (const float*)d_in[6];
    const float* W_gate  = (const float*)d_in[7];
    const float* b_gate  = (const float*)d_in[8];
    const float* iscale  = (const float*)d_in[9];
    const float* W_mag   = (const float*)d_in[10];
    const float* b_mag   = (const float*)d_in[11];
    const float* W_qoff  = (const float*)d_in[12];
    const float* b_qoff  = (const float*)d_in[13];
    const float* ln_g    = (const float*)d_in[14];
    const float* ln_b    = (const float*)d_in[15];
    const float* W_o1    = (const float*)d_in[16];
    const float* b_o1    = (const float*)d_in[17];
    const float* W_o2    = (const float*)d_in[18];
    const float* b_o2    = (const float*)d_in[19];
    float* out = (float*)d_out;

    __half *p_proj, *p_phii, *p_xf, *p_ctxf, *p_hf, *p_wf;
    float *p_bcat;
    float4 *p_csum, *p_coff;
    cudaGetSymbolAddress((void**)&p_proj,  g_proj);
    cudaGetSymbolAddress((void**)&p_phii,  g_phii);
    cudaGetSymbolAddress((void**)&p_xf,    g_xf);
    cudaGetSymbolAddress((void**)&p_ctxf,  g_ctxf);
    cudaGetSymbolAddress((void**)&p_hf,    g_hf);
    cudaGetSymbolAddress((void**)&p_wf,    g_wf);
    cudaGetSymbolAddress((void**)&p_bcat,  g_bcat);
    cudaGetSymbolAddress((void**)&p_csum,  g_csum);
    cudaGetSymbolAddress((void**)&p_coff,  g_coff);

    cudaFuncSetAttribute(mma_gemm<5,1>, cudaFuncAttributeMaxDynamicSharedMemorySize, SMEM_BYTES);
    cudaFuncSetAttribute(mma_gemm<0,1>, cudaFuncAttributeMaxDynamicSharedMemorySize, SMEM_BYTES);
    cudaFuncSetAttribute(mma_gemm<3,1>, cudaFuncAttributeMaxDynamicSharedMemorySize, SMEM_BYTES);
    cudaFuncSetAttribute(mma_gemm<4,0>, cudaFuncAttributeMaxDynamicSharedMemorySize, SMEM_BYTES);

    // Single prelude launch: all weight transposes + x conversion + bias concat
    prelude_kernel<<<WT_BLOCKS + FC_BLOCKS + (NPROJ + 255) / 256, dim3(32, 8)>>>(
        W_omega, W_mag, W_gate, W_qoff, W_p1, W_p2, W_o1, W_o2,
        x, b_omega, b_mag, b_gate, b_qoff, b_p1,
        p_wf, p_xf, p_bcat);

    const dim3 blk(256);

    // Fused 5-projection GEMM: [M,512] @ [512,2560] -> proj (segmented act)
    mma_gemm<5,1><<<dim3(NPROJ / 128, Mrows / 128), blk, SMEM_BYTES>>>(
        p_xf, p_wf + OFF_OM, p_bcat, 0, 0, p_proj, 512, 512, NPROJ);

    // p2: phi_init = p1seg @ W_p2 + b_p2  (A strided out of proj buffer)
    mma_gemm<0,1><<<dim3(4, Mrows / 128), blk, SMEM_BYTES>>>(
        p_proj + 2048, p_wf + OFF_P2, b_p2, 0, 0, p_phii, 512, NPROJ, 512);

    passA_kernel<<<Bdim * NC, 256>>>(p_xf, p_proj, p_phii, iscale, p_csum);
    passB_kernel<<<Bdim, Ddim>>>(p_csum, p_coff);
    passC_kernel<<<Bdim * NC, 256>>>(p_xf, p_proj, p_phii, iscale, ln_g, ln_b,
                                     p_coff, p_ctxf);

    mma_gemm<3,1><<<dim3(8, Mrows / 128), blk, SMEM_BYTES>>>(
        p_ctxf, p_wf + OFF_O1, b_o1, 0, 0, p_hf, 2048, 2048, 1024);
    mma_gemm<4,0><<<dim3(4, Mrows / 128), blk, SMEM_BYTES>>>(
        p_hf, p_wf + OFF_O2, b_o2, x, out, 0, 1024, 1024, 512);
}